// round 1
// baseline (speedup 1.0000x reference)
#include <cuda_runtime.h>

// Problem constants (fixed by the dataset)
#define LSEQ 2048
#define EDIM 64
#define NMODES 64
#define NBH 128        // B*H = 16*8
#define NCOL 128       // 2*NMODES (re | im)

// -------- device scratch (no allocation allowed) --------
__device__ float g_Ffq[LSEQ * NCOL];      // forward DFT matrix for q modes: [t][c], c<64: cos, c>=64: -sin
__device__ float g_Ffk[LSEQ * NCOL];      // forward DFT matrix for kv modes
__device__ float g_Binv[NCOL * LSEQ];     // inverse basis: [m][t]=cos, [64+m][t]=sin
__device__ float g_G[2 * NBH * 2 * EDIM * NMODES]; // [src(q/k)][bh][plane(re/im)][e][m]
__device__ float g_Y[NBH * 2 * NMODES * EDIM];     // [bh][plane][m][o]

// ---------------- init: twiddle tables ----------------
__global__ void k_init_tables(const int* __restrict__ idxq, const int* __restrict__ idxkv) {
    int idx = blockIdx.x * blockDim.x + threadIdx.x;   // 0 .. L*M-1
    if (idx >= LSEQ * NMODES) return;
    int t = idx >> 6, m = idx & 63;
    int fq = idxq[m];
    int fk = idxkv[m];
    int rq = (fq * t) & (LSEQ - 1);
    int rk = (fk * t) & (LSEQ - 1);
    float sq, cq, sk, ck;
    // theta = 2*pi*r/2048 = pi * (r/1024); r/1024 exact in fp32
    sincospif((float)rq * (1.0f / 1024.0f), &sq, &cq);
    sincospif((float)rk * (1.0f / 1024.0f), &sk, &ck);
    g_Ffq[t * NCOL + m]      = cq;
    g_Ffq[t * NCOL + 64 + m] = -sq;
    g_Ffk[t * NCOL + m]      = ck;
    g_Ffk[t * NCOL + 64 + m] = -sk;
    g_Binv[m * LSEQ + t]        = cq;
    g_Binv[(64 + m) * LSEQ + t] = sq;
}

// ---------------- K1: forward DFT GEMM ----------------
// One block per (src, b, h). C[64 e][128 c] = sum_t x[t,e] * F[t,c], K=2048.
__global__ void __launch_bounds__(256) k_fwd_dft(const float* __restrict__ q,
                                                 const float* __restrict__ k) {
    int bh2 = blockIdx.x;
    int src = bh2 >> 7;
    int bh  = bh2 & 127;
    int b = bh >> 3, h = bh & 7;
    const float* x  = (src == 0 ? q : k) + ((size_t)b * LSEQ * 8 + h) * 64;
    const float* Ff = (src == 0) ? g_Ffq : g_Ffk;

    __shared__ float As[16 * 64];    // x tile   [tk][e]
    __shared__ float Bs[16 * 128];   // F tile   [tk][c]

    int tid = threadIdx.x;
    int ty = tid >> 4, tx = tid & 15;

    float acc[4][8];
#pragma unroll
    for (int i = 0; i < 4; i++)
#pragma unroll
        for (int j = 0; j < 8; j++) acc[i][j] = 0.f;

    for (int t0 = 0; t0 < LSEQ; t0 += 16) {
        // A: 16 rows x 64 floats = 256 float4 (one per thread)
        {
            int row = tid >> 4, c4 = tid & 15;
            ((float4*)As)[tid] =
                *(const float4*)(x + (size_t)(t0 + row) * 512 + c4 * 4);
        }
        // B: 16 rows x 128 floats = 512 float4 (two per thread)
#pragma unroll
        for (int rep = 0; rep < 2; rep++) {
            int j = tid + rep * 256;
            int row = j >> 5, c4 = j & 31;
            ((float4*)Bs)[j] =
                *(const float4*)(Ff + (size_t)(t0 + row) * 128 + c4 * 4);
        }
        __syncthreads();
#pragma unroll
        for (int tk = 0; tk < 16; tk++) {
            float4 a  = *(float4*)&As[tk * 64 + ty * 4];
            float4 b0 = *(float4*)&Bs[tk * 128 + tx * 8];
            float4 b1 = *(float4*)&Bs[tk * 128 + tx * 8 + 4];
            float av[4] = {a.x, a.y, a.z, a.w};
            float bv[8] = {b0.x, b0.y, b0.z, b0.w, b1.x, b1.y, b1.z, b1.w};
#pragma unroll
            for (int i = 0; i < 4; i++)
#pragma unroll
                for (int j = 0; j < 8; j++)
                    acc[i][j] = fmaf(av[i], bv[j], acc[i][j]);
        }
        __syncthreads();
    }

    float* Gout = g_G + (size_t)(src * 128 + bh) * 8192;
#pragma unroll
    for (int i = 0; i < 4; i++) {
        int e = ty * 4 + i;
#pragma unroll
        for (int j = 0; j < 8; j++) {
            int c = tx * 8 + j;
            int p = c >> 6, m = c & 63;
            Gout[p * 4096 + e * 64 + m] = acc[i][j];
        }
    }
}

// ---------------- K2: projections, scores, tanh, apply, weights ----------------
// One block per (b,h). Dynamic smem: sA,sB,sC (8192 fl each) + sW (4096 fl) = 114688 B.
__global__ void __launch_bounds__(256) k_mid(
    const float* __restrict__ wq_w, const float* __restrict__ wq_b,
    const float* __restrict__ wk_w, const float* __restrict__ wk_b,
    const float* __restrict__ W1,   const float* __restrict__ W2,
    const int* __restrict__ idxq,   const int* __restrict__ idxkv) {
    extern __shared__ float sm[];
    float* sA = sm;            // Gq -> (P2) Xk
    float* sB = sm + 8192;     // Xq -> (P4) Z
    float* sC = sm + 16384;    // Gk -> (P3) S^T
    float* sW = sm + 24576;    // Wq then Wk

    int bh = blockIdx.x;
    int h  = bh & 7;
    int tid = threadIdx.x;

    const float* Gq = g_G + (size_t)bh * 8192;
    const float* Gk = g_G + (size_t)(128 + bh) * 8192;
    for (int i = tid; i < 8192; i += 256) sA[i] = Gq[i];
    for (int i = tid; i < 8192; i += 256) sC[i] = Gk[i];
    for (int i = tid; i < 4096; i += 256) sW[i] = wq_w[i];
    __syncthreads();

    // P1: Xq[e',m] = sum_e Wq[e',e] * Gq[e,m]  (+ bias at mode f==0)  -> sB
    for (int kk = 0; kk < 16; kk++) {
        int idx = kk * 256 + tid;
        int ep = idx >> 6, m = idx & 63;
        float ar = 0.f, ai = 0.f;
#pragma unroll 16
        for (int e = 0; e < 64; e++) {
            float w = sW[ep * 64 + e];
            ar = fmaf(w, sA[e * 64 + m], ar);
            ai = fmaf(w, sA[4096 + e * 64 + m], ai);
        }
        if (idxq[m] == 0) ar += 2048.f * wq_b[ep];
        sB[idx] = ar;
        sB[4096 + idx] = ai;
    }
    __syncthreads();
    for (int i = tid; i < 4096; i += 256) sW[i] = wk_w[i];
    __syncthreads();

    // P2: Xk[e',m] -> sA (overwrites Gq)
    for (int kk = 0; kk < 16; kk++) {
        int idx = kk * 256 + tid;
        int ep = idx >> 6, m = idx & 63;
        float ar = 0.f, ai = 0.f;
#pragma unroll 16
        for (int e = 0; e < 64; e++) {
            float w = sW[ep * 64 + e];
            ar = fmaf(w, sC[e * 64 + m], ar);
            ai = fmaf(w, sC[4096 + e * 64 + m], ai);
        }
        if (idxkv[m] == 0) ar += 2048.f * wk_b[ep];
        sA[idx] = ar;
        sA[4096 + idx] = ai;
    }
    __syncthreads();

    // P3: S[x,y] = sum_e Xq[e,x]*Xk[e,y] (complex), tanh parts, store S^T -> sC[y*64+x]
    for (int kk = 0; kk < 16; kk++) {
        int idx = kk * 256 + tid;      // idx == y*64 + x
        int x = idx & 63, y = idx >> 6;
        float sr = 0.f, si = 0.f;
#pragma unroll 16
        for (int e = 0; e < 64; e++) {
            float qr = sB[e * 64 + x], qi = sB[4096 + e * 64 + x];
            float kr = sA[e * 64 + y], ki = sA[4096 + e * 64 + y];
            sr = fmaf(qr, kr, sr); sr = fmaf(-qi, ki, sr);
            si = fmaf(qr, ki, si); si = fmaf(qi, kr, si);
        }
        sC[idx]        = tanhf(sr);
        sC[4096 + idx] = tanhf(si);
    }
    __syncthreads();

    // P4: Z[e,x] = sum_y S[x,y]*Xk[e,y] (complex*complex) -> sB (overwrites Xq)
    for (int kk = 0; kk < 16; kk++) {
        int idx = kk * 256 + tid;      // idx == e*64 + x
        int x = idx & 63, e = idx >> 6;
        float zr = 0.f, zi = 0.f;
#pragma unroll 8
        for (int y = 0; y < 64; y++) {
            float sr = sC[y * 64 + x], si = sC[4096 + y * 64 + x];
            float kr = sA[e * 64 + y], ki = sA[4096 + e * 64 + y];
            zr = fmaf(sr, kr, zr); zr = fmaf(-si, ki, zr);
            zi = fmaf(sr, ki, zi); zi = fmaf(si, kr, zi);
        }
        sB[idx]        = zr;
        sB[4096 + idx] = zi;
    }
    __syncthreads();

    // P5: Y[o,x] = sum_e Z[e,x] * (W1[h,e,o,x] + i*W2[h,e,o,x])  -> g_Y[bh][plane][x][o]
    const float* W1h = W1 + (size_t)h * 64 * 64 * 64;
    const float* W2h = W2 + (size_t)h * 64 * 64 * 64;
    float* Yout = g_Y + (size_t)bh * 8192;
    for (int kk = 0; kk < 16; kk++) {
        int idx = kk * 256 + tid;
        int x = idx & 63, o = idx >> 6;
        float yr = 0.f, yi = 0.f;
#pragma unroll 4
        for (int e = 0; e < 64; e++) {
            float zr = sB[e * 64 + x], zi = sB[4096 + e * 64 + x];
            float wr = W1h[(size_t)(e * 64 + o) * 64 + x];
            float wi = W2h[(size_t)(e * 64 + o) * 64 + x];
            yr = fmaf(zr, wr, yr); yr = fmaf(-zi, wi, yr);
            yi = fmaf(zr, wi, yi); yi = fmaf(zi, wr, yi);
        }
        Yout[x * 64 + o]        = yr;
        Yout[4096 + x * 64 + o] = yi;
    }
}

// ---------------- K3: inverse sparse DFT GEMM ----------------
// out[o,t] = sum_m Ar[o,m]*cos + Ai[o,m]*sin ; A folds 2/1/0 coeffs and 2^-29 scale.
__global__ void __launch_bounds__(256) k_inv_dft(float* __restrict__ out,
                                                 const int* __restrict__ idxq) {
    __shared__ float As[128 * 64];   // [k][o]
    __shared__ float Bs[16 * 128];   // [tk][t]

    int bh = blockIdx.y;
    int t0 = blockIdx.x * 128;
    int tid = threadIdx.x;
    int ty = tid >> 4, tx = tid & 15;

    const float* Y = g_Y + (size_t)bh * 8192;
    const float scale = 1.862645149230957e-9f;  // 2^-29
#pragma unroll
    for (int kk = 0; kk < 32; kk++) {
        int idx = kk * 256 + tid;   // [plane][m][o]
        int p = idx >> 12;
        int rem = idx & 4095;
        int m = rem >> 6, o = rem & 63;
        int f = idxq[m];
        float c;
        if (f == 0 || f == 1024) c = (p == 0) ? 1.f : 0.f;
        else                     c = 2.f;
        float v = Y[idx] * c * scale;
        if (p == 1) v = -v;          // -Im coefficient on the sin basis
        As[(p * 64 + m) * 64 + o] = v;
    }
    __syncthreads();

    float acc[4][8];
#pragma unroll
    for (int i = 0; i < 4; i++)
#pragma unroll
        for (int j = 0; j < 8; j++) acc[i][j] = 0.f;

    for (int kt = 0; kt < 8; kt++) {
#pragma unroll
        for (int rep = 0; rep < 2; rep++) {
            int j = tid + rep * 256;
            int row = j >> 5, c4 = j & 31;
            ((float4*)Bs)[j] =
                *(const float4*)(g_Binv + (size_t)(kt * 16 + row) * LSEQ + t0 + c4 * 4);
        }
        __syncthreads();
#pragma unroll
        for (int tk = 0; tk < 16; tk++) {
            float4 a  = *(float4*)&As[(kt * 16 + tk) * 64 + ty * 4];
            float4 b0 = *(float4*)&Bs[tk * 128 + tx * 8];
            float4 b1 = *(float4*)&Bs[tk * 128 + tx * 8 + 4];
            float av[4] = {a.x, a.y, a.z, a.w};
            float bv[8] = {b0.x, b0.y, b0.z, b0.w, b1.x, b1.y, b1.z, b1.w};
#pragma unroll
            for (int i = 0; i < 4; i++)
#pragma unroll
                for (int j = 0; j < 8; j++)
                    acc[i][j] = fmaf(av[i], bv[j], acc[i][j]);
        }
        __syncthreads();
    }

    float* op = out + (size_t)bh * 64 * LSEQ;
#pragma unroll
    for (int i = 0; i < 4; i++) {
        int o = ty * 4 + i;
        float4 v0 = make_float4(acc[i][0], acc[i][1], acc[i][2], acc[i][3]);
        float4 v1 = make_float4(acc[i][4], acc[i][5], acc[i][6], acc[i][7]);
        *(float4*)(op + (size_t)o * LSEQ + t0 + tx * 8)     = v0;
        *(float4*)(op + (size_t)o * LSEQ + t0 + tx * 8 + 4) = v1;
    }
}

// ---------------- launch ----------------
extern "C" void kernel_launch(void* const* d_in, const int* in_sizes, int n_in,
                              void* d_out, int out_size) {
    const float* q    = (const float*)d_in[0];
    const float* k    = (const float*)d_in[1];
    // d_in[2] = v : projected but unused downstream — skipped entirely
    const float* wq_w = (const float*)d_in[3];
    const float* wq_b = (const float*)d_in[4];
    const float* wk_w = (const float*)d_in[5];
    const float* wk_b = (const float*)d_in[6];
    // d_in[7], d_in[8] = wv_w, wv_b : unused
    const float* W1   = (const float*)d_in[9];
    const float* W2   = (const float*)d_in[10];
    const int*  idxq  = (const int*)d_in[11];
    const int*  idxkv = (const int*)d_in[12];
    float* out = (float*)d_out;

    k_init_tables<<<(LSEQ * NMODES + 255) / 256, 256>>>(idxq, idxkv);
    k_fwd_dft<<<256, 256>>>(q, k);
    cudaFuncSetAttribute(k_mid, cudaFuncAttributeMaxDynamicSharedMemorySize, 114688);
    k_mid<<<128, 256, 114688>>>(wq_w, wq_b, wk_w, wk_b, W1, W2, idxq, idxkv);
    k_inv_dft<<<dim3(16, 128), 256>>>(out, idxq);
}

// round 2
// speedup vs baseline: 1.5238x; 1.5238x over previous
#include <cuda_runtime.h>

#define LSEQ 2048
#define NBH 128
typedef unsigned long long ull;

// -------- device scratch --------
__device__ float g_Ffq[LSEQ * 128];   // [t][c] c<64: cos, c>=64: -sin (q modes)
__device__ float g_Ffk[LSEQ * 128];   // same for kv modes
__device__ float g_Binv[128 * LSEQ];  // [k][t]: k<64 cos, k>=64 sin
__device__ float g_G[2 * NBH * 8192]; // [src][bh][plane][e][m]
__device__ float g_Y[NBH * 8192];     // [bh][k][o]  (coefficients, pre-folded for irDFT)

// -------- f32x2 helpers --------
__device__ __forceinline__ ull dup2(float x) {
    ull r; asm("mov.b64 %0, {%1, %1};" : "=l"(r) : "f"(x)); return r;
}
__device__ __forceinline__ void fma2(ull& d, ull a, ull b) {
    asm("fma.rn.f32x2 %0, %1, %2, %3;" : "=l"(d) : "l"(a), "l"(b), "l"(d));
}
__device__ __forceinline__ float2 unpk(ull v) {
    float2 r; asm("mov.b64 {%0, %1}, %2;" : "=f"(r.x), "=f"(r.y) : "l"(v)); return r;
}
__device__ __forceinline__ ull neg2(ull v) { return v ^ 0x8000000080000000ULL; }

// ---------------- init: twiddle tables ----------------
__global__ void k_init_tables(const int* __restrict__ idxq, const int* __restrict__ idxkv) {
    int idx = blockIdx.x * blockDim.x + threadIdx.x;
    if (idx >= LSEQ * 64) return;
    int t = idx >> 6, m = idx & 63;
    int rq = (idxq[m] * t) & (LSEQ - 1);
    int rk = (idxkv[m] * t) & (LSEQ - 1);
    float sq, cq, sk, ck;
    sincospif((float)rq * (1.0f / 1024.0f), &sq, &cq);
    sincospif((float)rk * (1.0f / 1024.0f), &sk, &ck);
    g_Ffq[t * 128 + m]      = cq;
    g_Ffq[t * 128 + 64 + m] = -sq;
    g_Ffk[t * 128 + m]      = ck;
    g_Ffk[t * 128 + 64 + m] = -sk;
    g_Binv[m * LSEQ + t]        = cq;
    g_Binv[(64 + m) * LSEQ + t] = sq;
}

// ---------------- K1: forward DFT GEMM ----------------
// grid 512: (src, bh, chalf). Block 128 thr. Tile C[64 e][64 c], K=2048.
// Thread tile 8e x 4c (2 f32x2 pairs at c = j*32 + 2*tx).
__global__ void __launch_bounds__(128) k_fwd_dft(const float* __restrict__ q,
                                                 const float* __restrict__ k) {
    int bx = blockIdx.x;
    int chalf = bx & 1;
    int bh    = (bx >> 1) & 127;
    int src   = bx >> 8;
    const float* x  = (src == 0 ? q : k) + (size_t)(bh >> 3) * (LSEQ * 512) + (bh & 7) * 64;
    const float* Ff = ((src == 0) ? g_Ffq : g_Ffk) + chalf * 64;

    __shared__ float As[16 * 64];
    __shared__ float Bs[16 * 64];

    int tid = threadIdx.x;
    int ty = tid >> 4, tx = tid & 15;
    int rowA0 = tid >> 4,          colA0 = (tid & 15) * 4;
    int rowA1 = (tid + 128) >> 4,  colA1 = colA0;

    ull acc[8][2];
#pragma unroll
    for (int i = 0; i < 8; i++) { acc[i][0] = 0ULL; acc[i][1] = 0ULL; }

    float4 pA0, pA1, pB0, pB1;
    // prefetch chunk 0
    pA0 = *(const float4*)(x + (size_t)rowA0 * 512 + colA0);
    pA1 = *(const float4*)(x + (size_t)rowA1 * 512 + colA1);
    pB0 = *(const float4*)(Ff + (size_t)rowA0 * 128 + colA0);
    pB1 = *(const float4*)(Ff + (size_t)rowA1 * 128 + colA1);

    for (int it = 0; it < 128; it++) {
        __syncthreads();
        *(float4*)&As[rowA0 * 64 + colA0] = pA0;
        *(float4*)&As[rowA1 * 64 + colA1] = pA1;
        *(float4*)&Bs[rowA0 * 64 + colA0] = pB0;
        *(float4*)&Bs[rowA1 * 64 + colA1] = pB1;
        __syncthreads();
        if (it + 1 < 128) {
            int t0 = (it + 1) * 16;
            pA0 = *(const float4*)(x + (size_t)(t0 + rowA0) * 512 + colA0);
            pA1 = *(const float4*)(x + (size_t)(t0 + rowA1) * 512 + colA1);
            pB0 = *(const float4*)(Ff + (size_t)(t0 + rowA0) * 128 + colA0);
            pB1 = *(const float4*)(Ff + (size_t)(t0 + rowA1) * 128 + colA1);
        }
#pragma unroll
        for (int tk = 0; tk < 16; tk++) {
            float4 a0 = *(float4*)&As[tk * 64 + ty * 8];
            float4 a1 = *(float4*)&As[tk * 64 + ty * 8 + 4];
            ull b0 = *(ull*)&Bs[tk * 64 + tx * 2];
            ull b1 = *(ull*)&Bs[tk * 64 + 32 + tx * 2];
            ull ad[8] = {dup2(a0.x), dup2(a0.y), dup2(a0.z), dup2(a0.w),
                         dup2(a1.x), dup2(a1.y), dup2(a1.z), dup2(a1.w)};
#pragma unroll
            for (int i = 0; i < 8; i++) {
                fma2(acc[i][0], ad[i], b0);
                fma2(acc[i][1], ad[i], b1);
            }
        }
    }

    float* Gout = g_G + (size_t)(src * 128 + bh) * 8192 + chalf * 4096;
#pragma unroll
    for (int i = 0; i < 8; i++) {
        int e = ty * 8 + i;
        *(ull*)&Gout[e * 64 + tx * 2]      = acc[i][0];
        *(ull*)&Gout[e * 64 + 32 + tx * 2] = acc[i][1];
    }
}

// ---------------- K2: projections, scores, tanh, apply, weights ----------------
__global__ void __launch_bounds__(256) k_mid(
    const float* __restrict__ wq_w, const float* __restrict__ wq_b,
    const float* __restrict__ wk_w, const float* __restrict__ wk_b,
    const float* __restrict__ W1,   const float* __restrict__ W2,
    const int* __restrict__ idxq,   const int* __restrict__ idxkv) {
    extern __shared__ float sm[];
    float* sA = sm;            // Gq -> (P2) Xk
    float* sB = sm + 8192;     // Xq -> (P4) Z
    float* sC = sm + 16384;    // Gk -> (P3) S^T (tanh'd)
    float* sW = sm + 24576;    // Wq then Wk

    int bh = blockIdx.x;
    int h  = bh & 7;
    int tid = threadIdx.x;

    const float4* Gq4 = (const float4*)(g_G + (size_t)bh * 8192);
    const float4* Gk4 = (const float4*)(g_G + (size_t)(128 + bh) * 8192);
#pragma unroll
    for (int r = 0; r < 8; r++) {
        ((float4*)sA)[r * 256 + tid] = Gq4[r * 256 + tid];
        ((float4*)sC)[r * 256 + tid] = Gk4[r * 256 + tid];
    }
#pragma unroll
    for (int r = 0; r < 4; r++)
        ((float4*)sW)[r * 256 + tid] = ((const float4*)wq_w)[r * 256 + tid];
    __syncthreads();

    // P1: Xq[e',m] = sum_e Wq[e',e]*Gq[e,m] (+L*bias at f==0) -> sB (pairs over m)
#pragma unroll 1
    for (int kk = 0; kk < 8; kk++) {
        int pidx = kk * 256 + tid;
        int ep = pidx >> 5, mp = pidx & 31;
        ull ar = 0ULL, ai = 0ULL;
#pragma unroll 8
        for (int e = 0; e < 64; e++) {
            ull wd = dup2(sW[ep * 64 + e]);
            fma2(ar, wd, *(ull*)&sA[e * 64 + mp * 2]);
            fma2(ai, wd, *(ull*)&sA[4096 + e * 64 + mp * 2]);
        }
        float2 arf = unpk(ar), aif = unpk(ai);
        float bb = 2048.f * wq_b[ep];
        if (idxq[2 * mp] == 0)     arf.x += bb;
        if (idxq[2 * mp + 1] == 0) arf.y += bb;
        *(float2*)&sB[ep * 64 + mp * 2] = arf;
        *(float2*)&sB[4096 + ep * 64 + mp * 2] = aif;
    }
    __syncthreads();
#pragma unroll
    for (int r = 0; r < 4; r++)
        ((float4*)sW)[r * 256 + tid] = ((const float4*)wk_w)[r * 256 + tid];
    __syncthreads();

    // P2: Xk[e',m] -> sA
#pragma unroll 1
    for (int kk = 0; kk < 8; kk++) {
        int pidx = kk * 256 + tid;
        int ep = pidx >> 5, mp = pidx & 31;
        ull ar = 0ULL, ai = 0ULL;
#pragma unroll 8
        for (int e = 0; e < 64; e++) {
            ull wd = dup2(sW[ep * 64 + e]);
            fma2(ar, wd, *(ull*)&sC[e * 64 + mp * 2]);
            fma2(ai, wd, *(ull*)&sC[4096 + e * 64 + mp * 2]);
        }
        float2 arf = unpk(ar), aif = unpk(ai);
        float bb = 2048.f * wk_b[ep];
        if (idxkv[2 * mp] == 0)     arf.x += bb;
        if (idxkv[2 * mp + 1] == 0) arf.y += bb;
        *(float2*)&sA[ep * 64 + mp * 2] = arf;
        *(float2*)&sA[4096 + ep * 64 + mp * 2] = aif;
    }
    __syncthreads();

    // P3: S[x,y] = sum_e Xq[e,x]*Xk[e,y] complex, tanh parts, store S^T -> sC[y][x]
#pragma unroll 1
    for (int kk = 0; kk < 8; kk++) {
        int pidx = kk * 256 + tid;
        int y = pidx >> 5, xp = pidx & 31;
        ull sr = 0ULL, si = 0ULL;
#pragma unroll 8
        for (int e = 0; e < 64; e++) {
            ull qr = *(ull*)&sB[e * 64 + xp * 2];
            ull qi = *(ull*)&sB[4096 + e * 64 + xp * 2];
            float kr = sA[e * 64 + y], ki = sA[4096 + e * 64 + y];
            ull krd = dup2(kr), kid = dup2(ki), nkid = dup2(-ki);
            fma2(sr, qr, krd); fma2(sr, qi, nkid);
            fma2(si, qr, kid); fma2(si, qi, krd);
        }
        float2 srf = unpk(sr), sif = unpk(si);
        srf.x = tanhf(srf.x); srf.y = tanhf(srf.y);
        sif.x = tanhf(sif.x); sif.y = tanhf(sif.y);
        *(float2*)&sC[y * 64 + xp * 2] = srf;
        *(float2*)&sC[4096 + y * 64 + xp * 2] = sif;
    }
    __syncthreads();

    // P4: Z[e,x] = sum_y S[x,y]*Xk[e,y] complex -> sB
#pragma unroll 1
    for (int kk = 0; kk < 8; kk++) {
        int pidx = kk * 256 + tid;
        int e = pidx >> 5, xp = pidx & 31;
        ull zr = 0ULL, zi = 0ULL;
#pragma unroll 8
        for (int y = 0; y < 64; y++) {
            ull s_r = *(ull*)&sC[y * 64 + xp * 2];
            ull s_i = *(ull*)&sC[4096 + y * 64 + xp * 2];
            float kr = sA[e * 64 + y], ki = sA[4096 + e * 64 + y];
            ull krd = dup2(kr), kid = dup2(ki), nkid = dup2(-ki);
            fma2(zr, s_r, krd); fma2(zr, s_i, nkid);
            fma2(zi, s_r, kid); fma2(zi, s_i, krd);
        }
        *(float2*)&sB[e * 64 + xp * 2] = unpk(zr);
        *(float2*)&sB[4096 + e * 64 + xp * 2] = unpk(zi);
    }
    __syncthreads();

    // P5: Y[o,x] = sum_e Z[e,x]*(W1+iW2)[h,e,o,x]; fold irDFT coeffs; -> g_Y[bh][k][o]
    const float* W1h = W1 + (size_t)h * 262144;
    const float* W2h = W2 + (size_t)h * 262144;
    float* Yout = g_Y + (size_t)bh * 8192;
    const float SC = 1.862645149230957e-9f;  // 2^-29
#pragma unroll 1
    for (int kk = 0; kk < 8; kk++) {
        int pidx = kk * 256 + tid;
        int o = pidx >> 5, xp = pidx & 31;
        ull yr = 0ULL, yi = 0ULL;
#pragma unroll 4
        for (int e = 0; e < 64; e++) {
            ull zr = *(ull*)&sB[e * 64 + xp * 2];
            ull zi = *(ull*)&sB[4096 + e * 64 + xp * 2];
            ull wr = *(const ull*)(W1h + (size_t)(e * 64 + o) * 64 + xp * 2);
            ull wi = *(const ull*)(W2h + (size_t)(e * 64 + o) * 64 + xp * 2);
            fma2(yr, zr, wr); fma2(yr, neg2(zi), wi);
            fma2(yi, zr, wi); fma2(yi, zi, wr);
        }
        float2 yrf = unpk(yr), yif = unpk(yi);
        int x0 = 2 * xp, x1 = x0 + 1;
        int f0 = idxq[x0], f1 = idxq[x1];
        bool dc0 = (f0 == 0) | (f0 == 1024);
        bool dc1 = (f1 == 0) | (f1 == 1024);
        float ca0 = dc0 ? SC : 2.f * SC;
        float ca1 = dc1 ? SC : 2.f * SC;
        float cb0 = dc0 ? 0.f : -2.f * SC;
        float cb1 = dc1 ? 0.f : -2.f * SC;
        Yout[x0 * 64 + o]        = yrf.x * ca0;
        Yout[x1 * 64 + o]        = yrf.y * ca1;
        Yout[4096 + x0 * 64 + o] = yif.x * cb0;
        Yout[4096 + x1 * 64 + o] = yif.y * cb1;
    }
}

// ---------------- K3: inverse sparse DFT GEMM ----------------
// grid (16, 128). Block 128 thr. Tile C[64 o][128 t], K=128.
// Thread tile 8o x 8t (4 f32x2 pairs at t = j*32 + 2*tx).
__global__ void __launch_bounds__(128) k_inv_dft(float* __restrict__ out) {
    __shared__ float As[16 * 64];
    __shared__ float Bs[16 * 128];

    int bh = blockIdx.y;
    int t0 = blockIdx.x * 128;
    int tid = threadIdx.x;
    int ty = tid >> 4, tx = tid & 15;
    const float* Yb = g_Y + (size_t)bh * 8192;

    int rowA0 = tid >> 4,         colA0 = (tid & 15) * 4;
    int rowA1 = (tid + 128) >> 4;
    int rowB0 = tid >> 5,         colB0 = (tid & 31) * 4;

    ull acc[8][4];
#pragma unroll
    for (int i = 0; i < 8; i++)
#pragma unroll
        for (int j = 0; j < 4; j++) acc[i][j] = 0ULL;

    float4 pA0, pA1, pB[4];
    pA0 = *(const float4*)(Yb + (size_t)rowA0 * 64 + colA0);
    pA1 = *(const float4*)(Yb + (size_t)rowA1 * 64 + colA0);
#pragma unroll
    for (int r = 0; r < 4; r++)
        pB[r] = *(const float4*)(g_Binv + (size_t)(rowB0 + r * 4) * LSEQ + t0 + colB0);

    for (int kt = 0; kt < 8; kt++) {
        __syncthreads();
        *(float4*)&As[rowA0 * 64 + colA0] = pA0;
        *(float4*)&As[rowA1 * 64 + colA0] = pA1;
#pragma unroll
        for (int r = 0; r < 4; r++)
            *(float4*)&Bs[(rowB0 + r * 4) * 128 + colB0] = pB[r];
        __syncthreads();
        if (kt + 1 < 8) {
            int k0 = (kt + 1) * 16;
            pA0 = *(const float4*)(Yb + (size_t)(k0 + rowA0) * 64 + colA0);
            pA1 = *(const float4*)(Yb + (size_t)(k0 + rowA1) * 64 + colA0);
#pragma unroll
            for (int r = 0; r < 4; r++)
                pB[r] = *(const float4*)(g_Binv + (size_t)(k0 + rowB0 + r * 4) * LSEQ + t0 + colB0);
        }
#pragma unroll
        for (int tk = 0; tk < 16; tk++) {
            float4 a0 = *(float4*)&As[tk * 64 + ty * 8];
            float4 a1 = *(float4*)&As[tk * 64 + ty * 8 + 4];
            ull bv[4];
#pragma unroll
            for (int j = 0; j < 4; j++) bv[j] = *(ull*)&Bs[tk * 128 + j * 32 + tx * 2];
            ull ad[8] = {dup2(a0.x), dup2(a0.y), dup2(a0.z), dup2(a0.w),
                         dup2(a1.x), dup2(a1.y), dup2(a1.z), dup2(a1.w)};
#pragma unroll
            for (int i = 0; i < 8; i++)
#pragma unroll
                for (int j = 0; j < 4; j++) fma2(acc[i][j], ad[i], bv[j]);
        }
    }

    float* op = out + (size_t)bh * 64 * LSEQ + t0;
#pragma unroll
    for (int i = 0; i < 8; i++) {
        int o = ty * 8 + i;
#pragma unroll
        for (int j = 0; j < 4; j++)
            *(ull*)(op + (size_t)o * LSEQ + j * 32 + tx * 2) = acc[i][j];
    }
}

// ---------------- launch ----------------
extern "C" void kernel_launch(void* const* d_in, const int* in_sizes, int n_in,
                              void* d_out, int out_size) {
    const float* q    = (const float*)d_in[0];
    const float* k    = (const float*)d_in[1];
    const float* wq_w = (const float*)d_in[3];
    const float* wq_b = (const float*)d_in[4];
    const float* wk_w = (const float*)d_in[5];
    const float* wk_b = (const float*)d_in[6];
    const float* W1   = (const float*)d_in[9];
    const float* W2   = (const float*)d_in[10];
    const int*  idxq  = (const int*)d_in[11];
    const int*  idxkv = (const int*)d_in[12];
    float* out = (float*)d_out;

    k_init_tables<<<(LSEQ * 64 + 255) / 256, 256>>>(idxq, idxkv);
    k_fwd_dft<<<512, 128>>>(q, k);
    cudaFuncSetAttribute(k_mid, cudaFuncAttributeMaxDynamicSharedMemorySize, 114688);
    k_mid<<<128, 256, 114688>>>(wq_w, wq_b, wk_w, wk_b, W1, W2, idxq, idxkv);
    k_inv_dft<<<dim3(16, 128), 128>>>(out);
}